// round 16
// baseline (speedup 1.0000x reference)
#include <cuda_runtime.h>
#include <cstdint>

#define T_TOKENS 16384
#define DIMX     2048
#define NE       8
#define KSEL     2048

// libdevice exp — exact bits, immune to fast-math flags.
extern "C" __device__ float __nv_expf(float);

// cp.async primitives (LDGSTS.128)
#define CP_ASYNC16(dst_u32, src_ptr) \
    asm volatile("cp.async.cg.shared.global [%0], [%1], 16;" :: "r"(dst_u32), "l"(src_ptr))
#define CP_COMMIT() asm volatile("cp.async.commit_group;" ::: "memory")
#define CP_WAIT2()  asm volatile("cp.async.wait_group 2;" ::: "memory")

// Scratch. g_hist is zero at load and re-zeroed by k2a each call (replay-safe);
// g_scan / g_meta / g_sel / g_bnd are fully rewritten each call before use.
__device__ unsigned int        g_keys[NE * T_TOKENS];
__device__ unsigned int        g_hist[NE * 16384];
__device__ unsigned int        g_scan[NE * 16384];
__device__ unsigned long long  g_sel [NE * KSEL];
__device__ unsigned long long  g_bnd [NE * 16384];
__device__ int                 g_meta[NE * 4];   // {bnd_bin, want, excl_bnd, cnt}

// ---------------------------------------------------------------------------
// Kernel 1: logits + keys + global 14-bit key-histogram. (R14, unchanged:
// cp.async 4-stage ring, one barrier/chunk, bitwise-stable in-order fma.rn.)
// ---------------------------------------------------------------------------
#define K1T     128
#define TILE    64
#define CH      32
#define XP      36
#define STGF    (TILE * XP)
#define NSTG    4
#define WPP     4100

__global__ void __launch_bounds__(K1T) k1_gemv(const float* __restrict__ x,
                                               const float* __restrict__ W)
{
    extern __shared__ float sm[];
    float* swp = sm;                         // [4][WPP]  packed pairs, 65.6KB
    float* sx  = sm + 4 * WPP;               // [4][STGF] ring, 36.9KB

    const int tid  = threadIdx.x;
    const int lane = tid & 31;
    const int P    = tid >> 5;
    const int e0   = 2 * P, e1 = e0 + 1;
    const size_t rowBase = (size_t)blockIdx.x * TILE;

    {
        const float4* W0 = reinterpret_cast<const float4*>(W + e0 * DIMX);
        const float4* W1 = reinterpret_cast<const float4*>(W + e1 * DIMX);
        float* dst = swp + P * WPP;
#pragma unroll 4
        for (int it = 0; it < 16; ++it) {
            int d4 = it * 32 + lane;
            float4 w0 = W0[d4];
            float4 w1 = W1[d4];
            float4* dp = reinterpret_cast<float4*>(dst + d4 * 8);
            dp[0] = make_float4(w0.x, w1.x, w0.y, w1.y);
            dp[1] = make_float4(w0.z, w1.z, w0.w, w1.w);
        }
    }

    int rr[4], cc[4];
    unsigned sdst[4];
#pragma unroll
    for (int k = 0; k < 4; ++k) {
        int idx = tid + k * K1T;
        rr[k] = idx >> 3;
        cc[k] = idx & 7;
        sdst[k] = (unsigned)__cvta_generic_to_shared(&sx[rr[k] * XP + cc[k] * 4]);
    }

    const float* xb = x + rowBase * DIMX;

#pragma unroll
    for (int s = 0; s < NSTG - 1; ++s) {
#pragma unroll
        for (int k = 0; k < 4; ++k)
            CP_ASYNC16(sdst[k] + s * (STGF * 4),
                       xb + (size_t)rr[k] * DIMX + s * CH + cc[k] * 4);
        CP_COMMIT();
    }

    float a00 = 0.0f, a01 = 0.0f, a10 = 0.0f, a11 = 0.0f;
    const float* wb0 = swp + P * WPP;

    for (int ch = 0; ch < DIMX / CH; ++ch) {
        CP_WAIT2();
        __syncthreads();

        if (ch + NSTG - 1 < DIMX / CH) {
            const int s = (ch + NSTG - 1) & (NSTG - 1);
#pragma unroll
            for (int k = 0; k < 4; ++k)
                CP_ASYNC16(sdst[k] + s * (STGF * 4),
                           xb + (size_t)rr[k] * DIMX + (ch + NSTG - 1) * CH + cc[k] * 4);
        }
        CP_COMMIT();

        const float* x0p = sx + (ch & (NSTG - 1)) * STGF + lane * XP;
        const float* x1p = x0p + 32 * XP;
        const float* wb  = wb0 + ch * (CH * 2);
#pragma unroll
        for (int g = 0; g < 8; ++g) {
            float4 x0 = *reinterpret_cast<const float4*>(x0p + g * 4);
            float4 x1 = *reinterpret_cast<const float4*>(x1p + g * 4);
            float4 wA = *reinterpret_cast<const float4*>(wb + g * 8);
            float4 wB = *reinterpret_cast<const float4*>(wb + g * 8 + 4);
            a00 = __fmaf_rn(x0.x, wA.x, a00);  a01 = __fmaf_rn(x0.x, wA.y, a01);
            a10 = __fmaf_rn(x1.x, wA.x, a10);  a11 = __fmaf_rn(x1.x, wA.y, a11);
            a00 = __fmaf_rn(x0.y, wA.z, a00);  a01 = __fmaf_rn(x0.y, wA.w, a01);
            a10 = __fmaf_rn(x1.y, wA.z, a10);  a11 = __fmaf_rn(x1.y, wA.w, a11);
            a00 = __fmaf_rn(x0.z, wB.x, a00);  a01 = __fmaf_rn(x0.z, wB.y, a01);
            a10 = __fmaf_rn(x1.z, wB.x, a10);  a11 = __fmaf_rn(x1.z, wB.y, a11);
            a00 = __fmaf_rn(x0.w, wB.z, a00);  a01 = __fmaf_rn(x0.w, wB.w, a01);
            a10 = __fmaf_rn(x1.w, wB.z, a10);  a11 = __fmaf_rn(x1.w, wB.w, a11);
        }
    }

    const int t0 = (int)rowBase + lane;
    const int t1 = t0 + 32;
    float acc[4] = {a00, a01, a10, a11};
    const int eid[4] = {e0, e1, e0, e1};
    const int tok[4] = {t0, t0, t1, t1};
#pragma unroll
    for (int u = 0; u < 4; ++u) {
        float em = __nv_expf(-acc[u]);
        float s  = __fdiv_rn(1.0f, __fadd_rn(1.0f, em));
        unsigned key = ~__float_as_uint(s);
        g_keys[eid[u] * T_TOKENS + tok[u]] = key;
        unsigned h = (unsigned)eid[u] * 16384u + (key >> 18);
        unsigned m = __match_any_sync(0xffffffffu, h);
        if ((int)lane == __ffs(m) - 1)
            atomicAdd(&g_hist[h], (unsigned)__popc(m));
    }
}

// ---------------------------------------------------------------------------
// Kernel 2a (8 blocks): scan g_hist -> exclusive starts g_scan, boundary
// meta, rezero g_hist. No key pass.
// ---------------------------------------------------------------------------
__global__ void __launch_bounds__(1024) k2a_scan()
{
    __shared__ unsigned int s_wsum[32];
    __shared__ int s_bin;
    __shared__ unsigned int s_before;

    const int e    = blockIdx.x;
    const int tid  = threadIdx.x;
    const unsigned lane = tid & 31;
    const int wid  = tid >> 5;

    unsigned v[16];
    {
        const uint4* gh = reinterpret_cast<const uint4*>(g_hist + e * 16384);
#pragma unroll
        for (int q = 0; q < 4; ++q) {
            uint4 u = gh[tid * 4 + q];
            v[q * 4 + 0] = u.x; v[q * 4 + 1] = u.y;
            v[q * 4 + 2] = u.z; v[q * 4 + 3] = u.w;
        }
        uint4* gz = reinterpret_cast<uint4*>(g_hist + e * 16384);
        uint4 z = make_uint4(0u, 0u, 0u, 0u);
#pragma unroll
        for (int q = 0; q < 4; ++q) gz[tid * 4 + q] = z;
    }
    unsigned lsum = 0;
#pragma unroll
    for (int j = 0; j < 16; ++j) lsum += v[j];

    unsigned si = lsum;
#pragma unroll
    for (int o = 1; o < 32; o <<= 1) {
        unsigned n = __shfl_up_sync(0xffffffffu, si, o);
        if (lane >= (unsigned)o) si += n;
    }
    if (lane == 31) s_wsum[wid] = si;
    __syncthreads();
    if (wid == 0) {
        unsigned w = s_wsum[lane];
        unsigned wi = w;
#pragma unroll
        for (int o = 1; o < 32; o <<= 1) {
            unsigned n = __shfl_up_sync(0xffffffffu, wi, o);
            if (lane >= (unsigned)o) wi += n;
        }
        s_wsum[lane] = wi - w;
    }
    __syncthreads();
    unsigned run = s_wsum[wid] + (si - lsum);

    unsigned outv[16];
#pragma unroll
    for (int j = 0; j < 16; ++j) {
        outv[j] = run;
        unsigned c = v[j];
        if ((int)run < KSEL && (int)(run + c) >= KSEL) {
            s_bin = tid * 16 + j;
            s_before = run;
        }
        run += c;
    }
    {
        uint4* gs = reinterpret_cast<uint4*>(g_scan + e * 16384);
#pragma unroll
        for (int q = 0; q < 4; ++q)
            gs[tid * 4 + q] = make_uint4(outv[q * 4], outv[q * 4 + 1],
                                         outv[q * 4 + 2], outv[q * 4 + 3]);
    }
    __syncthreads();
    if (tid == 0) {
        g_meta[e * 4 + 0] = s_bin;
        g_meta[e * 4 + 1] = KSEL - (int)s_before;   // want
        g_meta[e * 4 + 2] = (int)s_before;          // excl_bnd
        g_meta[e * 4 + 3] = 0;                      // boundary count
    }
}

// ---------------------------------------------------------------------------
// Kernel 2b (64 blocks = 8 experts x 8 slices): select + scatter.
// bin < bnd: final-region scatter via atomic bump of g_scan[bin];
// bin == bnd: append to g_bnd.
// ---------------------------------------------------------------------------
__global__ void __launch_bounds__(256) k2b_scatter()
{
    const int b   = blockIdx.x;
    const int e   = b >> 3;
    const int sl  = b & 7;
    const int tid = threadIdx.x;
    const int bnd = g_meta[e * 4 + 0];

    const unsigned* gk = g_keys + e * T_TOKENS + sl * 2048;
    unsigned* gs = g_scan + e * 16384;

#pragma unroll
    for (int r = 0; r < 8; ++r) {
        int i = tid + r * 256;
        unsigned key = gk[i];
        int bin = (int)(key >> 18);
        if (bin <= bnd) {
            unsigned long long K = ((unsigned long long)key << 14)
                                 | (unsigned)(sl * 2048 + i);
            if (bin < bnd) {
                unsigned pos = atomicAdd(&gs[bin], 1u);
                g_sel[e * KSEL + pos] = K;
            } else {
                int pos = atomicAdd(&g_meta[e * 4 + 3], 1);
                g_bnd[e * 16384 + pos] = K;
            }
        }
    }
}

// ---------------------------------------------------------------------------
// Kernel 2c (64 blocks = 8 experts x 8 output-chunks): emit final output.
// Non-boundary outputs: within-segment comparison rank over smem-resident
// selected keys (segment bounds from the post-scatter g_scan invariant:
// for bin < bnd, g_scan[bin] = segment end, g_scan[bin-1] = segment start).
// Boundary outputs: comparison rank over g_bnd (smem if m fits).
// ---------------------------------------------------------------------------
#define BNDSM 3584

__global__ void __launch_bounds__(256) k2c_emit(float* __restrict__ out, int writeIdx)
{
    __shared__ unsigned long long ssel[KSEL];     // 16 KB
    __shared__ unsigned long long sbnd[BNDSM];    // 28 KB

    const int b   = blockIdx.x;
    const int e   = b >> 3;
    const int j   = b & 7;
    const int tid = threadIdx.x;

    const int want  = g_meta[e * 4 + 1];
    const int exclb = g_meta[e * 4 + 2];
    const int m     = g_meta[e * 4 + 3];

    for (int i = tid; i < exclb; i += 256)
        ssel[i] = g_sel[e * KSEL + i];
    const bool bsm = (m <= BNDSM);
    if (bsm)
        for (int i = tid; i < m; i += 256)
            sbnd[i] = g_bnd[e * 16384 + i];
    __syncthreads();

    // Part 1: non-boundary output slot i.
    {
        int i = j * 256 + tid;
        if (i < exclb) {
            unsigned long long K = ssel[i];
            unsigned bin = (unsigned)(K >> 32);   // top-14 bits of key32
            unsigned s  = (bin > 0) ? g_scan[e * 16384 + bin - 1] : 0u;
            unsigned en = g_scan[e * 16384 + bin];
            unsigned rank = 0;
            for (unsigned q = s; q < en; ++q)
                rank += (ssel[q] < K) ? 1u : 0u;
            unsigned p = s + rank;
            out[e * KSEL + p] = __uint_as_float(~(unsigned)(K >> 14));
            if (writeIdx)
                out[NE * KSEL + e * KSEL + p] = (float)(unsigned)(K & 0x3FFFu);
        }
    }

    // Part 2: boundary keys (this block handles keys j*256+tid, +2048, ...).
    for (int kk = j * 256 + tid; kk < m; kk += 2048) {
        unsigned long long K = bsm ? sbnd[kk] : g_bnd[e * 16384 + kk];
        unsigned rank = 0;
        if (bsm) {
            for (int q = 0; q < m; ++q)
                rank += (sbnd[q] < K) ? 1u : 0u;
        } else {
            const unsigned long long* gb = g_bnd + e * 16384;
            for (int q = 0; q < m; ++q)
                rank += (gb[q] < K) ? 1u : 0u;
        }
        if ((int)rank < want) {
            unsigned p = (unsigned)exclb + rank;
            out[e * KSEL + p] = __uint_as_float(~(unsigned)(K >> 14));
            if (writeIdx)
                out[NE * KSEL + e * KSEL + p] = (float)(unsigned)(K & 0x3FFFu);
        }
    }
}

// ---------------------------------------------------------------------------
extern "C" void kernel_launch(void* const* d_in, const int* in_sizes, int n_in,
                              void* d_out, int out_size)
{
    const float* x = (const float*)d_in[0];   // [16384, 2048] f32
    const float* W = (const float*)d_in[1];   // [8, 2048] f32
    float* out = (float*)d_out;

    const int SMEM1 = (4 * WPP + NSTG * STGF) * (int)sizeof(float);   // 102464
    cudaFuncSetAttribute(k1_gemv, cudaFuncAttributeMaxDynamicSharedMemorySize, SMEM1);

    const int writeIdx = (out_size >= 2 * NE * KSEL) ? 1 : 0;

    k1_gemv<<<T_TOKENS / TILE, K1T, SMEM1>>>(x, W);   // logits + keys + hist
    k2a_scan<<<NE, 1024>>>();                          // scan + meta + rezero
    k2b_scatter<<<NE * 8, 256>>>();                    // chip-wide select+scatter
    k2c_emit<<<NE * 8, 256>>>(out, writeIdx);          // chip-wide rank+emit
}

// round 17
// speedup vs baseline: 1.2193x; 1.2193x over previous
#include <cuda_runtime.h>
#include <cstdint>

#define T_TOKENS 16384
#define DIMX     2048
#define NE       8
#define KSEL     2048

// libdevice exp — exact bits, immune to fast-math flags.
extern "C" __device__ float __nv_expf(float);

// cp.async primitives (LDGSTS.128)
#define CP_ASYNC16(dst_u32, src_ptr) \
    asm volatile("cp.async.cg.shared.global [%0], [%1], 16;" :: "r"(dst_u32), "l"(src_ptr))
#define CP_COMMIT() asm volatile("cp.async.commit_group;" ::: "memory")
#define CP_WAIT2()  asm volatile("cp.async.wait_group 2;" ::: "memory")

// Scratch. g_hist zero at load, re-zeroed by k2 each call (replay-safe).
// g_sel is a per-expert spill buffer for the (rare) n>6144 case.
__device__ unsigned int       g_keys[NE * T_TOKENS];
__device__ unsigned int       g_hist[NE * 16384];
__device__ unsigned long long g_sel [NE * T_TOKENS];

// ---------------------------------------------------------------------------
// Kernel 1: logits + keys + global 14-bit key-histogram. (R14, byte-identical:
// cp.async 4-stage ring, one barrier/chunk, bitwise-stable in-order fma.rn.)
// ---------------------------------------------------------------------------
#define K1T     128
#define TILE    64
#define CH      32
#define XP      36
#define STGF    (TILE * XP)
#define NSTG    4
#define WPP     4100

__global__ void __launch_bounds__(K1T) k1_gemv(const float* __restrict__ x,
                                               const float* __restrict__ W)
{
    extern __shared__ float sm[];
    float* swp = sm;                         // [4][WPP]  packed pairs, 65.6KB
    float* sx  = sm + 4 * WPP;               // [4][STGF] ring, 36.9KB

    const int tid  = threadIdx.x;
    const int lane = tid & 31;
    const int P    = tid >> 5;
    const int e0   = 2 * P, e1 = e0 + 1;
    const size_t rowBase = (size_t)blockIdx.x * TILE;

    {
        const float4* W0 = reinterpret_cast<const float4*>(W + e0 * DIMX);
        const float4* W1 = reinterpret_cast<const float4*>(W + e1 * DIMX);
        float* dst = swp + P * WPP;
#pragma unroll 4
        for (int it = 0; it < 16; ++it) {
            int d4 = it * 32 + lane;
            float4 w0 = W0[d4];
            float4 w1 = W1[d4];
            float4* dp = reinterpret_cast<float4*>(dst + d4 * 8);
            dp[0] = make_float4(w0.x, w1.x, w0.y, w1.y);
            dp[1] = make_float4(w0.z, w1.z, w0.w, w1.w);
        }
    }

    int rr[4], cc[4];
    unsigned sdst[4];
#pragma unroll
    for (int k = 0; k < 4; ++k) {
        int idx = tid + k * K1T;
        rr[k] = idx >> 3;
        cc[k] = idx & 7;
        sdst[k] = (unsigned)__cvta_generic_to_shared(&sx[rr[k] * XP + cc[k] * 4]);
    }

    const float* xb = x + rowBase * DIMX;

#pragma unroll
    for (int s = 0; s < NSTG - 1; ++s) {
#pragma unroll
        for (int k = 0; k < 4; ++k)
            CP_ASYNC16(sdst[k] + s * (STGF * 4),
                       xb + (size_t)rr[k] * DIMX + s * CH + cc[k] * 4);
        CP_COMMIT();
    }

    float a00 = 0.0f, a01 = 0.0f, a10 = 0.0f, a11 = 0.0f;
    const float* wb0 = swp + P * WPP;

    for (int ch = 0; ch < DIMX / CH; ++ch) {
        CP_WAIT2();
        __syncthreads();

        if (ch + NSTG - 1 < DIMX / CH) {
            const int s = (ch + NSTG - 1) & (NSTG - 1);
#pragma unroll
            for (int k = 0; k < 4; ++k)
                CP_ASYNC16(sdst[k] + s * (STGF * 4),
                           xb + (size_t)rr[k] * DIMX + (ch + NSTG - 1) * CH + cc[k] * 4);
        }
        CP_COMMIT();

        const float* x0p = sx + (ch & (NSTG - 1)) * STGF + lane * XP;
        const float* x1p = x0p + 32 * XP;
        const float* wb  = wb0 + ch * (CH * 2);
#pragma unroll
        for (int g = 0; g < 8; ++g) {
            float4 x0 = *reinterpret_cast<const float4*>(x0p + g * 4);
            float4 x1 = *reinterpret_cast<const float4*>(x1p + g * 4);
            float4 wA = *reinterpret_cast<const float4*>(wb + g * 8);
            float4 wB = *reinterpret_cast<const float4*>(wb + g * 8 + 4);
            a00 = __fmaf_rn(x0.x, wA.x, a00);  a01 = __fmaf_rn(x0.x, wA.y, a01);
            a10 = __fmaf_rn(x1.x, wA.x, a10);  a11 = __fmaf_rn(x1.x, wA.y, a11);
            a00 = __fmaf_rn(x0.y, wA.z, a00);  a01 = __fmaf_rn(x0.y, wA.w, a01);
            a10 = __fmaf_rn(x1.y, wA.z, a10);  a11 = __fmaf_rn(x1.y, wA.w, a11);
            a00 = __fmaf_rn(x0.z, wB.x, a00);  a01 = __fmaf_rn(x0.z, wB.y, a01);
            a10 = __fmaf_rn(x1.z, wB.x, a10);  a11 = __fmaf_rn(x1.z, wB.y, a11);
            a00 = __fmaf_rn(x0.w, wB.z, a00);  a01 = __fmaf_rn(x0.w, wB.w, a01);
            a10 = __fmaf_rn(x1.w, wB.z, a10);  a11 = __fmaf_rn(x1.w, wB.w, a11);
        }
    }

    const int t0 = (int)rowBase + lane;
    const int t1 = t0 + 32;
    float acc[4] = {a00, a01, a10, a11};
    const int eid[4] = {e0, e1, e0, e1};
    const int tok[4] = {t0, t0, t1, t1};
#pragma unroll
    for (int u = 0; u < 4; ++u) {
        float em = __nv_expf(-acc[u]);
        float s  = __fdiv_rn(1.0f, __fadd_rn(1.0f, em));
        unsigned key = ~__float_as_uint(s);
        g_keys[eid[u] * T_TOKENS + tok[u]] = key;
        unsigned h = (unsigned)eid[u] * 16384u + (key >> 18);
        unsigned m = __match_any_sync(0xffffffffu, h);
        if ((int)lane == __ffs(m) - 1)
            atomicAdd(&g_hist[h], (unsigned)__popc(m));
    }
}

// ---------------------------------------------------------------------------
// Kernel 2: per-expert exact top-2048 (desc, ties -> lower index).
// Candidates = all keys in 14-bit bins <= boundary bin (the n smallest keys,
// n in [2048, 2048+bndcount)). Rank them exactly via a data-adaptive fine
// counting sort: binf = (key - kmin) >> sh with sh sized to the candidate
// range, scatter by atomic bin-bump, within-segment comparison rank
// (segments ~1 elem). Emit ranks < 2048. No Kstar, no bitonic sort.
// ---------------------------------------------------------------------------
#define K2_THREADS 1024
#define SELSM      6144

__global__ void __launch_bounds__(K2_THREADS) k2_topk(float* __restrict__ out, int writeIdx)
{
    extern __shared__ unsigned char sm2[];
    unsigned int*       hist = reinterpret_cast<unsigned int*>(sm2);            // 64KB
    unsigned long long* ssel = reinterpret_cast<unsigned long long*>(sm2 + 65536); // 48KB

    __shared__ unsigned int s_wsum[32];
    __shared__ int          s_bnd;
    __shared__ int          s_ntot;
    __shared__ unsigned int s_kmin;
    __shared__ int          s_sh;

    const int e    = blockIdx.x;
    const int tid  = threadIdx.x;
    const unsigned lane = tid & 31;
    const int wid  = tid >> 5;

    // Keys in registers: kreg[r] = key of token (tid + r*1024).
    unsigned kreg[16];
    {
        const unsigned* gk = g_keys + e * T_TOKENS;
#pragma unroll
        for (int r = 0; r < 16; ++r)
            kreg[r] = gk[tid + r * K2_THREADS];
    }

    // ---- Level 0: scan g_hist (14-bit bins) -> boundary bin + n; rezero ----
    {
        unsigned v[16];
        {
            const uint4* gh = reinterpret_cast<const uint4*>(g_hist + e * 16384);
#pragma unroll
            for (int q = 0; q < 4; ++q) {
                uint4 u = gh[tid * 4 + q];
                v[q * 4 + 0] = u.x; v[q * 4 + 1] = u.y;
                v[q * 4 + 2] = u.z; v[q * 4 + 3] = u.w;
            }
            uint4* gz = reinterpret_cast<uint4*>(g_hist + e * 16384);
            uint4 z = make_uint4(0u, 0u, 0u, 0u);
#pragma unroll
            for (int q = 0; q < 4; ++q) gz[tid * 4 + q] = z;
        }
        unsigned lsum = 0;
#pragma unroll
        for (int j = 0; j < 16; ++j) lsum += v[j];

        unsigned si = lsum;
#pragma unroll
        for (int o = 1; o < 32; o <<= 1) {
            unsigned n = __shfl_up_sync(0xffffffffu, si, o);
            if (lane >= (unsigned)o) si += n;
        }
        if (lane == 31) s_wsum[wid] = si;
        __syncthreads();
        if (wid == 0) {
            unsigned w = s_wsum[lane];
            unsigned wi = w;
#pragma unroll
            for (int o = 1; o < 32; o <<= 1) {
                unsigned n = __shfl_up_sync(0xffffffffu, wi, o);
                if (lane >= (unsigned)o) wi += n;
            }
            s_wsum[lane] = wi - w;
        }
        __syncthreads();
        unsigned run = s_wsum[wid] + (si - lsum);
#pragma unroll
        for (int j = 0; j < 16; ++j) {
            unsigned c = v[j];
            if ((int)run < KSEL && (int)(run + c) >= KSEL) {
                s_bnd  = tid * 16 + j;
                s_ntot = (int)(run + c);
            }
            run += c;
        }
        __syncthreads();
    }
    const unsigned bnd = (unsigned)s_bnd;
    const int n = s_ntot;

    // ---- Block-min key -> adaptive shift ----
    {
        unsigned km = 0xFFFFFFFFu;
#pragma unroll
        for (int r = 0; r < 16; ++r) km = umin(km, kreg[r]);
#pragma unroll
        for (int o = 16; o >= 1; o >>= 1)
            km = umin(km, __shfl_xor_sync(0xffffffffu, km, o));
        if (lane == 0) s_wsum[wid] = km;
        __syncthreads();
        if (wid == 0) {
            unsigned w = s_wsum[lane];
#pragma unroll
            for (int o = 16; o >= 1; o >>= 1)
                w = umin(w, __shfl_xor_sync(0xffffffffu, w, o));
            if (lane == 0) s_kmin = w;
        }
        __syncthreads();
        if (tid == 0) {
            unsigned long long top   = ((unsigned long long)(bnd + 1)) << 18;
            unsigned long long range = top - (unsigned long long)s_kmin; // >= 1
            int bits = 64 - __clzll(range);
            s_sh = (bits > 14) ? (bits - 14) : 0;
        }
        __syncthreads();
    }
    const unsigned kmin = s_kmin;
    const int      sh   = s_sh;

    // ---- Fine histogram over candidates (bins monotone in key) ----
    for (int i = tid; i < 16384; i += K2_THREADS) hist[i] = 0u;
    __syncthreads();
#pragma unroll
    for (int r = 0; r < 16; ++r) {
        unsigned key = kreg[r];
        if ((key >> 18) <= bnd)
            atomicAdd(&hist[(key - kmin) >> sh], 1u);
    }
    __syncthreads();

    // ---- Exclusive scan of fine hist (in place: hist becomes starts) ----
    {
        unsigned v[16];
#pragma unroll
        for (int j = 0; j < 16; ++j) v[j] = hist[tid * 16 + j];
        unsigned lsum = 0;
#pragma unroll
        for (int j = 0; j < 16; ++j) lsum += v[j];
        unsigned si = lsum;
#pragma unroll
        for (int o = 1; o < 32; o <<= 1) {
            unsigned nn = __shfl_up_sync(0xffffffffu, si, o);
            if (lane >= (unsigned)o) si += nn;
        }
        if (lane == 31) s_wsum[wid] = si;
        __syncthreads();
        if (wid == 0) {
            unsigned w = s_wsum[lane];
            unsigned wi = w;
#pragma unroll
            for (int o = 1; o < 32; o <<= 1) {
                unsigned nn = __shfl_up_sync(0xffffffffu, wi, o);
                if (lane >= (unsigned)o) wi += nn;
            }
            s_wsum[lane] = wi - w;
        }
        __syncthreads();
        unsigned run = s_wsum[wid] + (si - lsum);
#pragma unroll
        for (int j = 0; j < 16; ++j) {
            hist[tid * 16 + j] = run;   // exclusive start
            run += v[j];
        }
        __syncthreads();
    }

    // ---- Scatter candidates by fine bin (atomic bump of starts) ----
    unsigned long long* dst = (n <= SELSM) ? ssel : (g_sel + e * T_TOKENS);
#pragma unroll
    for (int r = 0; r < 16; ++r) {
        unsigned key = kreg[r];
        if ((key >> 18) <= bnd) {
            unsigned long long K = ((unsigned long long)key << 14)
                                 | (unsigned)(tid + r * K2_THREADS);
            unsigned pos = atomicAdd(&hist[(key - kmin) >> sh], 1u);
            dst[pos] = K;
        }
    }
    __syncthreads();
    // Post-scatter: hist[b] = segment end; hist[b-1] = segment start.

    // ---- Fixup rank + emit (segments avg ~1 element) ----
    for (int i = tid; i < n; i += K2_THREADS) {
        unsigned long long K = dst[i];
        unsigned key = (unsigned)(K >> 14);
        unsigned bf  = (key - kmin) >> sh;
        unsigned s   = (bf > 0) ? hist[bf - 1] : 0u;
        unsigned en  = hist[bf];
        unsigned rank = 0;
        for (unsigned q = s; q < en; ++q)
            rank += (dst[q] < K) ? 1u : 0u;
        unsigned p = s + rank;
        if ((int)p < KSEL) {
            out[e * KSEL + p] = __uint_as_float(~key);
            if (writeIdx)
                out[NE * KSEL + e * KSEL + p] = (float)(unsigned)(K & 0x3FFFu);
        }
    }
}

// ---------------------------------------------------------------------------
extern "C" void kernel_launch(void* const* d_in, const int* in_sizes, int n_in,
                              void* d_out, int out_size)
{
    const float* x = (const float*)d_in[0];   // [16384, 2048] f32
    const float* W = (const float*)d_in[1];   // [8, 2048] f32
    float* out = (float*)d_out;

    const int SMEM1 = (4 * WPP + NSTG * STGF) * (int)sizeof(float);   // 102464
    const int SMEM2 = 65536 + SELSM * 8;                              // 114688

    cudaFuncSetAttribute(k1_gemv, cudaFuncAttributeMaxDynamicSharedMemorySize, SMEM1);
    cudaFuncSetAttribute(k2_topk, cudaFuncAttributeMaxDynamicSharedMemorySize, SMEM2);

    const int writeIdx = (out_size >= 2 * NE * KSEL) ? 1 : 0;

    k1_gemv<<<T_TOKENS / TILE, K1T, SMEM1>>>(x, W);   // logits + keys + hist
    k2_topk<<<NE, K2_THREADS, SMEM2>>>(out, writeIdx); // adaptive counting top-k
}